// round 2
// baseline (speedup 1.0000x reference)
#include <cuda_runtime.h>

// Output layout (floats), tuple order (c_all, y_all, GBT_A, GBT_B):
//   c_all : [1024,256]      offset 0        size 262144
//   y_all : [1024]          offset 262144   size 1024
//   GBT_A : [1024,256,256]  offset 263168   size 67108864
//   GBT_B : [1024,256]      offset 67372032 size 262144
#define OC 0
#define OY 262144
#define OA 263168
#define OB 67372032

static __device__ __forceinline__ float frcp(float x) {
    float y; asm("rcp.approx.ftz.f32 %0,%1;" : "=f"(y) : "f"(x)); return y;
}

__global__ __launch_bounds__(256) void hippo_fused(
    const float* __restrict__ f,
    const float* __restrict__ init_state,
    const float* __restrict__ Bv,
    float* __restrict__ out)
{
    const int bid = blockIdx.x;
    const int tid = threadIdx.x;

    if (bid < 256) {
        // ================= GBT_A: 4 timesteps per block =================
        // Ad_k lower triangular. Column j:
        //   diag   = (1 - h(j+1)) / d_j
        //   first  = -2h r_{j+1} r_j / (d_j d_{j+1})
        //   ratio  t_i = r_i (1 - h(i-1)) / (r_{i-1} d_i)   (j-independent)
        __shared__ float t_sh[4][256];
        const int grp = tid >> 6;       // which timestep in this block
        const int g   = tid & 63;       // thread within group (owns 4 cols)
        const int k   = (bid << 2) + grp;
        const float s = frcp((float)(k + 1));
        const float h = 0.5f * s;

        #pragma unroll
        for (int m = 0; m < 4; m++) {
            int i = g + (m << 6);
            float tv = 0.0f;
            if (i >= 1) {
                float ri  = __ldg(Bv + i);
                float rim = __ldg(Bv + i - 1);
                float di  = fmaf(h, (float)(i + 1), 1.0f);
                tv = ri * (1.0f - h * (float)(i - 1)) * frcp(rim * di);
            }
            t_sh[grp][i] = tv;
        }
        __syncthreads();

        const int j0 = g << 2;
        float invd[5];
        #pragma unroll
        for (int m = 0; m < 5; m++)
            invd[m] = frcp(fmaf(h, (float)(j0 + m + 1), 1.0f));

        float diag[4], start[4], val[4];
        #pragma unroll
        for (int m = 0; m < 4; m++) {
            int j = j0 + m;
            diag[m] = (1.0f - h * (float)(j + 1)) * invd[m];
            float rj  = __ldg(Bv + j);
            float rj1 = (j + 1 < 256) ? __ldg(Bv + j + 1) : 0.0f;
            start[m] = -2.0f * h * rj1 * rj * invd[m] * invd[m + 1];
            val[m] = 0.0f;
        }

        float4* outp = (float4*)(out + OA + ((size_t)k << 16) + j0);
        for (int i = 0; i < 256; i++) {
            float tv = t_sh[grp][i];
            float4 v;
            #pragma unroll
            for (int m = 0; m < 4; m++) {
                int j = j0 + m;
                val[m] = (i == j + 1) ? start[m] : val[m] * tv;  // stays 0 until i==j+1
                float vv = (i < j) ? 0.0f : ((i == j) ? diag[m] : val[m]);
                ((float*)&v)[m] = vv;
            }
            outp[(size_t)i << 6] = v;  // row i, cols j0..j0+3 (coalesced 128-bit)
        }
    } else if (bid == 256) {
        // ================= systolic scan: c_all + y_all =================
        // c_k = P1_k^{-1}(2 c_{k-1} + s_k f_k B) - c_{k-1}; O(N) solve via
        //   x_i = (u_i - h r_i S_i)/d_i ;  S_{i+1} = S_i + r_i x_i
        // lane l owns element i=l; iteration t handles timestep k = t - l.
        __shared__ float2 tab[1024];   // (s_k, s_k*f_k)
        __shared__ float2 bnd[2][8];   // warp-boundary (S, ypartial), double buffered
        const int w = tid >> 5, lane = tid & 31;

        for (int kk = tid; kk < 1024; kk += 256) {
            float sk = frcp((float)(kk + 1));
            tab[kk] = make_float2(sk, sk * f[kk]);
        }
        if (tid < 16) ((float2*)bnd)[tid] = make_float2(0.0f, 0.0f);

        const float r    = __ldg(Bv + tid);       // r_i = B_i
        const float fip1 = (float)(tid + 1);
        float c = init_state[tid];
        float Scur = 0.0f, ycur = 0.0f;
        __syncthreads();

        int k = -tid;
        for (int t = 0; t < 1279; t++, k++) {
            bool valid = ((unsigned)k < 1024u);
            float2 ssf = tab[valid ? k : 0];
            float h    = 0.5f * ssf.x;
            float invd = frcp(fmaf(h, fip1, 1.0f));
            float u    = fmaf(ssf.y, r, c + c);          // 2c + s f B_i
            float hr   = h * r;
            float x    = fmaf(-hr, Scur, u) * invd;
            float So   = fmaf(r, x, Scur);
            float cn   = x - c;
            float yo   = ycur + cn;
            if (valid) {
                c = cn;
                out[OC + ((size_t)k << 8) + tid] = cn;
                if (tid == 255) out[OY + k] = yo;         // y_k completes at element 255
            }
            float Ssh = __shfl_up_sync(0xffffffffu, So, 1);
            float ysh = __shfl_up_sync(0xffffffffu, yo, 1);
            if (lane == 31) bnd[t & 1][w] = make_float2(So, yo);
            __syncthreads();
            if (lane == 0) {
                if (w == 0) { Ssh = 0.0f; ysh = 0.0f; }
                else { float2 b = bnd[t & 1][w - 1]; Ssh = b.x; ysh = b.y; }
            }
            Scur = Ssh; ycur = ysh;
        }
    } else {
        // ================= GBT_B: thread per timestep =================
        __shared__ float rsh[256];
        rsh[tid] = __ldg(Bv + tid);
        __syncthreads();
        const int k = ((bid - 257) << 8) + tid;
        const float s = frcp((float)(k + 1));
        const float h = 0.5f * s;
        float S = 0.0f;
        float* outB = out + OB + ((size_t)k << 8);
        for (int i = 0; i < 256; i++) {
            float r    = rsh[i];
            float invd = frcp(fmaf(h, (float)(i + 1), 1.0f));
            float x    = r * fmaf(-h, S, 1.0f) * invd;   // (r_i - h r_i S)/d_i
            outB[i] = s * x;
            S = fmaf(r, x, S);
        }
    }
}

extern "C" void kernel_launch(void* const* d_in, const int* in_sizes, int n_in,
                              void* d_out, int out_size) {
    const float* f          = (const float*)d_in[0];
    const float* init_state = (const float*)d_in[1];
    const float* Bv         = (const float*)d_in[3];
    hippo_fused<<<261, 256>>>(f, init_state, Bv, (float*)d_out);
}